// round 1
// baseline (speedup 1.0000x reference)
#include <cuda_runtime.h>
#include <cuda_bf16.h>
#include <math.h>

// Problem constants
#define B 8
#define L 2500
#define D 512
#define Y 8921

// Device scratch for per-row BCE terms (no cudaMalloc allowed)
__device__ float g_bce[B * Y];

// ---------------------------------------------------------------------------
// Packed f32x2 helpers (Blackwell FFMA2 — only reachable via PTX)
// ---------------------------------------------------------------------------
__device__ __forceinline__ unsigned long long pack2(float lo, float hi) {
    unsigned long long r;
    asm("mov.b64 %0, {%1, %2};" : "=l"(r) : "f"(lo), "f"(hi));
    return r;
}
__device__ __forceinline__ void fma2(unsigned long long& d,
                                     unsigned long long a,
                                     unsigned long long b) {
    asm("fma.rn.f32x2 %0, %1, %2, %0;" : "+l"(d) : "l"(a), "l"(b));
}
__device__ __forceinline__ void unpack2(unsigned long long v, float& lo, float& hi) {
    asm("mov.b64 {%0, %1}, %2;" : "=f"(lo), "=f"(hi) : "l"(v));
}

// ---------------------------------------------------------------------------
// GEMM1: scores[b,y,l] = sum_d U_w[y,d] * x[b,l,d]
// A = U_w [Y,D] K-major, B = x[b] [L,D] K-major. 128x128x16 tile, 256 thr,
// 8x8 per thread via f32x2 packed FMA.
// ---------------------------------------------------------------------------
__global__ __launch_bounds__(256)
void gemm_scores(const float* __restrict__ Uw,
                 const float* __restrict__ x,
                 float* __restrict__ scores) {
    const int b  = blockIdx.z;
    const int m0 = blockIdx.y * 128;   // over Y
    const int n0 = blockIdx.x * 128;   // over L

    __shared__ float As[16][132];
    __shared__ float Bs[16][132];

    const float* xb = x + (size_t)b * L * D;
    const int tid = threadIdx.x;
    const int tx = tid & 15;
    const int ty = tid >> 4;

    unsigned long long acc[8][4];
#pragma unroll
    for (int i = 0; i < 8; i++)
#pragma unroll
        for (int p = 0; p < 4; p++) acc[i][p] = 0ull;

    for (int kt = 0; kt < D; kt += 16) {
        // Load A tile (128 rows x 16 k), 2 float4 per thread, transpose to As[k][m]
#pragma unroll
        for (int it = 0; it < 2; it++) {
            int f   = tid + it * 256;
            int row = f >> 2;
            int kq  = (f & 3) * 4;
            float4 v = make_float4(0.f, 0.f, 0.f, 0.f);
            int gm = m0 + row;
            if (gm < Y) v = *reinterpret_cast<const float4*>(&Uw[(size_t)gm * D + kt + kq]);
            As[kq + 0][row] = v.x; As[kq + 1][row] = v.y;
            As[kq + 2][row] = v.z; As[kq + 3][row] = v.w;
        }
        // Load B tile (128 rows(l) x 16 k), transpose to Bs[k][l]
#pragma unroll
        for (int it = 0; it < 2; it++) {
            int f   = tid + it * 256;
            int row = f >> 2;
            int kq  = (f & 3) * 4;
            float4 v = make_float4(0.f, 0.f, 0.f, 0.f);
            int gl = n0 + row;
            if (gl < L) v = *reinterpret_cast<const float4*>(&xb[(size_t)gl * D + kt + kq]);
            Bs[kq + 0][row] = v.x; Bs[kq + 1][row] = v.y;
            Bs[kq + 2][row] = v.z; Bs[kq + 3][row] = v.w;
        }
        __syncthreads();

#pragma unroll
        for (int k = 0; k < 16; k++) {
            const float* ap = &As[k][ty * 8];
            const float* bp = &Bs[k][tx * 8];
            float4 a0 = *reinterpret_cast<const float4*>(ap);
            float4 a1 = *reinterpret_cast<const float4*>(ap + 4);
            ulonglong2 bq0 = *reinterpret_cast<const ulonglong2*>(bp);
            ulonglong2 bq1 = *reinterpret_cast<const ulonglong2*>(bp + 4);
            unsigned long long rb[4] = {bq0.x, bq0.y, bq1.x, bq1.y};
            unsigned long long ra[8];
            ra[0] = pack2(a0.x, a0.x); ra[1] = pack2(a0.y, a0.y);
            ra[2] = pack2(a0.z, a0.z); ra[3] = pack2(a0.w, a0.w);
            ra[4] = pack2(a1.x, a1.x); ra[5] = pack2(a1.y, a1.y);
            ra[6] = pack2(a1.z, a1.z); ra[7] = pack2(a1.w, a1.w);
#pragma unroll
            for (int i = 0; i < 8; i++)
#pragma unroll
                for (int p = 0; p < 4; p++) fma2(acc[i][p], ra[i], rb[p]);
        }
        __syncthreads();
    }

    float* sb = scores + (size_t)b * Y * L;
#pragma unroll
    for (int i = 0; i < 8; i++) {
        int gm = m0 + ty * 8 + i;
        if (gm >= Y) continue;
        float* rowp = sb + (size_t)gm * L;
#pragma unroll
        for (int p = 0; p < 4; p++) {
            float lo, hi;
            unpack2(acc[i][p], lo, hi);
            int gl = n0 + tx * 8 + 2 * p;
            if (gl < L)     rowp[gl]     = lo;
            if (gl + 1 < L) rowp[gl + 1] = hi;
        }
    }
}

// ---------------------------------------------------------------------------
// Softmax over L for each of B*Y rows (in place). 256 threads / row.
// ---------------------------------------------------------------------------
__global__ __launch_bounds__(256)
void softmax_rows(float* __restrict__ a) {
    const int row = blockIdx.x;
    float* p = a + (size_t)row * L;
    const int tid = threadIdx.x;

    float vals[10];
    int cnt = 0;
    float mx = -INFINITY;
    for (int i = tid; i < L; i += 256) {
        float v = p[i];
        vals[cnt++] = v;
        mx = fmaxf(mx, v);
    }
    __shared__ float red[256];
    red[tid] = mx; __syncthreads();
    for (int s = 128; s > 0; s >>= 1) {
        if (tid < s) red[tid] = fmaxf(red[tid], red[tid + s]);
        __syncthreads();
    }
    mx = red[0];
    __syncthreads();

    float sum = 0.f;
    for (int c = 0; c < cnt; c++) {
        vals[c] = expf(vals[c] - mx);
        sum += vals[c];
    }
    red[tid] = sum; __syncthreads();
    for (int s = 128; s > 0; s >>= 1) {
        if (tid < s) red[tid] += red[tid + s];
        __syncthreads();
    }
    float inv = 1.0f / red[0];

    cnt = 0;
    for (int i = tid; i < L; i += 256) p[i] = vals[cnt++] * inv;
}

// ---------------------------------------------------------------------------
// GEMM2: m[b,y,d] = sum_l alpha[b,y,l] * x[b,l,d]
// A = alpha [Y,L] K-major (scalar loads: base is 4B-aligned only),
// B = x[b] [L,D] N-major. 128x128x16 tile, same packed-FMA inner loop.
// ---------------------------------------------------------------------------
__global__ __launch_bounds__(256)
void gemm_m(const float* __restrict__ alpha,
            const float* __restrict__ x,
            float* __restrict__ mout) {
    const int b  = blockIdx.z;
    const int m0 = blockIdx.y * 128;   // over Y
    const int n0 = blockIdx.x * 128;   // over D (exactly 4 tiles)

    __shared__ float As[16][132];
    __shared__ float Bs[16][128];

    const float* ab = alpha + (size_t)b * Y * L;
    const float* xb = x + (size_t)b * L * D;
    const int tid = threadIdx.x;
    const int tx = tid & 15;
    const int ty = tid >> 4;

    unsigned long long acc[8][4];
#pragma unroll
    for (int i = 0; i < 8; i++)
#pragma unroll
        for (int p = 0; p < 4; p++) acc[i][p] = 0ull;

    for (int kt = 0; kt < L; kt += 16) {
        // A tile: 128 rows x 16 k, scalar (unaligned base), transpose
#pragma unroll
        for (int it = 0; it < 8; it++) {
            int e = tid + it * 256;
            int row = e >> 4;
            int k   = e & 15;
            int gm = m0 + row;
            int gk = kt + k;
            float v = 0.f;
            if (gm < Y && gk < L) v = ab[(size_t)gm * L + gk];
            As[k][row] = v;
        }
        // B tile: 16 rows(l) x 128 cols(d), vectorized, natural layout
#pragma unroll
        for (int it = 0; it < 2; it++) {
            int f  = tid + it * 256;
            int kr = f >> 5;
            int nc = (f & 31) * 4;
            int gk = kt + kr;
            float4 v = make_float4(0.f, 0.f, 0.f, 0.f);
            if (gk < L) v = *reinterpret_cast<const float4*>(&xb[(size_t)gk * D + n0 + nc]);
            *reinterpret_cast<float4*>(&Bs[kr][nc]) = v;
        }
        __syncthreads();

#pragma unroll
        for (int k = 0; k < 16; k++) {
            const float* ap = &As[k][ty * 8];
            const float* bp = &Bs[k][tx * 8];
            float4 a0 = *reinterpret_cast<const float4*>(ap);
            float4 a1 = *reinterpret_cast<const float4*>(ap + 4);
            ulonglong2 bq0 = *reinterpret_cast<const ulonglong2*>(bp);
            ulonglong2 bq1 = *reinterpret_cast<const ulonglong2*>(bp + 4);
            unsigned long long rb[4] = {bq0.x, bq0.y, bq1.x, bq1.y};
            unsigned long long ra[8];
            ra[0] = pack2(a0.x, a0.x); ra[1] = pack2(a0.y, a0.y);
            ra[2] = pack2(a0.z, a0.z); ra[3] = pack2(a0.w, a0.w);
            ra[4] = pack2(a1.x, a1.x); ra[5] = pack2(a1.y, a1.y);
            ra[6] = pack2(a1.z, a1.z); ra[7] = pack2(a1.w, a1.w);
#pragma unroll
            for (int i = 0; i < 8; i++)
#pragma unroll
                for (int p = 0; p < 4; p++) fma2(acc[i][p], ra[i], rb[p]);
        }
        __syncthreads();
    }

    float* mb = mout + (size_t)b * Y * D;
#pragma unroll
    for (int i = 0; i < 8; i++) {
        int gm = m0 + ty * 8 + i;
        if (gm >= Y) continue;
        float* rowp = mb + (size_t)gm * D;
#pragma unroll
        for (int p = 0; p < 4; p++) {
            float lo, hi;
            unpack2(acc[i][p], lo, hi);
            int gn = n0 + tx * 8 + 2 * p;
            rowp[gn]     = lo;
            rowp[gn + 1] = hi;
        }
    }
}

// ---------------------------------------------------------------------------
// Final: y[r] = dot(final_w[i], m[r]) + final_b[i]; per-row BCE term.
// One block (128 thr) per row r = b*Y + i.
// ---------------------------------------------------------------------------
__global__ __launch_bounds__(128)
void final_kernel(const float* __restrict__ mrr,
                  const float* __restrict__ fw,
                  const float* __restrict__ fb,
                  const float* __restrict__ target,
                  float* __restrict__ out_y) {
    const int r = blockIdx.x;
    const int i = r % Y;
    const float* mp = mrr + (size_t)r * D;
    const float* wp = fw + (size_t)i * D;
    const int tid = threadIdx.x;

    float s = 0.f;
    for (int d = tid; d < D; d += 128) s = fmaf(wp[d], mp[d], s);
#pragma unroll
    for (int off = 16; off > 0; off >>= 1) s += __shfl_down_sync(0xffffffffu, s, off);

    __shared__ float sh[4];
    if ((tid & 31) == 0) sh[tid >> 5] = s;
    __syncthreads();
    if (tid == 0) {
        float yv = sh[0] + sh[1] + sh[2] + sh[3] + fb[i];
        out_y[r] = yv;
        float t = target[r];
        g_bce[r] = fmaxf(yv, 0.f) - yv * t + log1pf(expf(-fabsf(yv)));
    }
}

__global__ __launch_bounds__(256)
void loss_reduce(float* __restrict__ out_loss) {
    __shared__ double sh[256];
    double s = 0.0;
    for (int i = threadIdx.x; i < B * Y; i += 256) s += (double)g_bce[i];
    sh[threadIdx.x] = s;
    __syncthreads();
    for (int st = 128; st > 0; st >>= 1) {
        if (threadIdx.x < st) sh[threadIdx.x] += sh[threadIdx.x + st];
        __syncthreads();
    }
    if (threadIdx.x == 0) out_loss[0] = (float)(sh[0] / (double)(B * Y));
}

// ---------------------------------------------------------------------------
// Launch. Output layout: [y (B*Y), loss (1), alpha (B*Y*L), m (B*Y*D)]
// ---------------------------------------------------------------------------
extern "C" void kernel_launch(void* const* d_in, const int* in_sizes, int n_in,
                              void* d_out, int out_size) {
    const float* x      = (const float*)d_in[0];
    const float* target = (const float*)d_in[1];
    // d_in[2] = text_inputs (unused by the reference computation)
    const float* Uw     = (const float*)d_in[3];
    const float* fw     = (const float*)d_in[4];
    const float* fb     = (const float*)d_in[5];

    float* out       = (float*)d_out;
    float* out_y     = out;
    float* out_loss  = out + (size_t)B * Y;
    float* out_alpha = out_loss + 1;
    float* out_m     = out_alpha + (size_t)B * Y * L;

    dim3 g1((L + 127) / 128, (Y + 127) / 128, B);   // 20 x 70 x 8
    gemm_scores<<<g1, 256>>>(Uw, x, out_alpha);

    softmax_rows<<<B * Y, 256>>>(out_alpha);

    dim3 g2(D / 128, (Y + 127) / 128, B);           // 4 x 70 x 8
    gemm_m<<<g2, 256>>>(out_alpha, x, out_m);

    final_kernel<<<B * Y, 128>>>(out_m, fw, fb, target, out_y);
    loss_reduce<<<1, 256>>>(out_loss);
}

// round 4
// speedup vs baseline: 2.0745x; 2.0745x over previous
#include <cuda_runtime.h>
#include <cuda_bf16.h>
#include <math.h>
#include <stdint.h>

// Problem constants
#define B 8
#define L 2500
#define D 512
#define Y 8921
#define LP 2560            // L padded to a multiple of 64 (K of GEMM2)

// Shared-memory tile geometry (bf16, padded rows for conflict-free ldmatrix)
#define AROW 72                       // 64 data + 8 pad bf16 elems (144 B rows)
#define MAT_ELEMS (128 * AROW)        // one 128x64 operand matrix
#define MAT_BYTES (MAT_ELEMS * 2)     // 18432 B
#define STAGE_BYTES (4 * MAT_BYTES)   // Ah, Al, Bh, Bl = 73728 B
#define SMEM_BYTES (2 * STAGE_BYTES)  // 2-stage pipeline = 147456 B

// ---------------------------------------------------------------------------
// Device scratch (no cudaMalloc allowed)
// ---------------------------------------------------------------------------
__device__ __align__(16) __nv_bfloat16 g_x_hi[(size_t)B * L * D];
__device__ __align__(16) __nv_bfloat16 g_x_lo[(size_t)B * L * D];
__device__ __align__(16) __nv_bfloat16 g_xT_hi[(size_t)B * D * LP];
__device__ __align__(16) __nv_bfloat16 g_xT_lo[(size_t)B * D * LP];
__device__ __align__(16) __nv_bfloat16 g_U_hi[(size_t)Y * D];
__device__ __align__(16) __nv_bfloat16 g_U_lo[(size_t)Y * D];
__device__ __align__(16) __nv_bfloat16 g_a_hi[(size_t)B * Y * LP];
__device__ __align__(16) __nv_bfloat16 g_a_lo[(size_t)B * Y * LP];
__device__ float g_bce[B * Y];

// ---------------------------------------------------------------------------
// PTX helpers (all base-sm_103-legal: cp.async, ldmatrix, mma.sync)
// ---------------------------------------------------------------------------
__device__ __forceinline__ uint32_t smem_u32(const void* p) {
    uint32_t a;
    asm("{ .reg .u64 t; cvta.to.shared.u64 t, %1; cvt.u32.u64 %0, t; }"
        : "=r"(a) : "l"(p));
    return a;
}

__device__ __forceinline__ void cpa16(uint32_t dst, const void* src, int szbytes) {
    asm volatile("cp.async.cg.shared.global [%0], [%1], 16, %2;"
                 :: "r"(dst), "l"(src), "r"(szbytes) : "memory");
}
__device__ __forceinline__ void cpa_commit() {
    asm volatile("cp.async.commit_group;" ::: "memory");
}
template <int N>
__device__ __forceinline__ void cpa_wait() {
    asm volatile("cp.async.wait_group %0;" :: "n"(N) : "memory");
}

__device__ __forceinline__ void ldsm4(uint32_t* r, uint32_t addr) {
    asm volatile("ldmatrix.sync.aligned.m8n8.x4.shared.b16 {%0,%1,%2,%3}, [%4];"
                 : "=r"(r[0]), "=r"(r[1]), "=r"(r[2]), "=r"(r[3]) : "r"(addr));
}

__device__ __forceinline__ void mma16816(float* c, const uint32_t* a,
                                         uint32_t b0, uint32_t b1) {
    asm volatile(
        "mma.sync.aligned.m16n8k16.row.col.f32.bf16.bf16.f32 "
        "{%0,%1,%2,%3}, {%4,%5,%6,%7}, {%8,%9}, {%0,%1,%2,%3};"
        : "+f"(c[0]), "+f"(c[1]), "+f"(c[2]), "+f"(c[3])
        : "r"(a[0]), "r"(a[1]), "r"(a[2]), "r"(a[3]), "r"(b0), "r"(b1));
}

// ---------------------------------------------------------------------------
// Chunk loader: 4 matrices (Ah, Al, Bh, Bl), each 128 rows x 64 bf16, via
// cp.async 16B. Rows >= nvalid are zero-filled (src-size 0).
// ---------------------------------------------------------------------------
__device__ __forceinline__ void load_chunk(uint32_t s_addr,
        const __nv_bfloat16* __restrict__ Ah, const __nv_bfloat16* __restrict__ Al,
        size_t sA, int nA,
        const __nv_bfloat16* __restrict__ Bh, const __nv_bfloat16* __restrict__ Bl,
        size_t sB, int nB, int tid) {
    const __nv_bfloat16* srcs[4] = {Ah, Al, Bh, Bl};
    const int    nvs[4] = {nA, nA, nB, nB};
    const size_t sts[4] = {sA, sA, sB, sB};
#pragma unroll
    for (int m = 0; m < 4; m++) {
#pragma unroll
        for (int it = 0; it < 4; it++) {
            int idx = tid + it * 256;
            int r = idx >> 3, u = idx & 7;
            uint32_t dst = s_addr + m * MAT_BYTES + (uint32_t)(r * AROW + u * 8) * 2;
            bool ok = r < nvs[m];
            const void* src = srcs[m] + (ok ? ((size_t)r * sts[m] + u * 8) : 0);
            cpa16(dst, src, ok ? 16 : 0);
        }
    }
}

// ---------------------------------------------------------------------------
// Core GEMM: C[m<=128, n<=128] = sum_k (Ah+Al)[m,k]*(Bh+Bl)[n,k] (drop lo*lo)
// 256 threads, 8 warps in 4(M) x 2(N); warp tile 32x64; m16n8k16 bf16 mma.
// ---------------------------------------------------------------------------
template <int CHUNKS>
__device__ __forceinline__ void gemm_core(
    const __nv_bfloat16* __restrict__ Ah, const __nv_bfloat16* __restrict__ Al,
    size_t sA, int nA,
    const __nv_bfloat16* __restrict__ Bh, const __nv_bfloat16* __restrict__ Bl,
    size_t sB, int nB,
    float* __restrict__ Co, size_t sC, int nrow, int ncol)
{
    extern __shared__ __align__(16) char smem[];
    const uint32_t sb = smem_u32(smem);
    const int tid = threadIdx.x;
    const int lane = tid & 31;
    const int wid = tid >> 5;
    const int warp_m = wid >> 1;     // 0..3 -> 32-row slabs
    const int warp_n = wid & 1;      // 0..1 -> 64-col slabs

    // ldmatrix per-lane source row/col selection (x4 layout)
    const int rowsel = (lane & 7) + ((lane >> 3) & 1) * 8;
    const int colsel = (lane >> 4) & 1;

    uint32_t aoff[2], boff[4];
#pragma unroll
    for (int im = 0; im < 2; im++)
        aoff[im] = (uint32_t)(((warp_m * 32 + im * 16 + rowsel) * AROW + colsel * 8) * 2);
#pragma unroll
    for (int jn = 0; jn < 4; jn++)
        boff[jn] = (uint32_t)(((warp_n * 64 + jn * 16 + rowsel) * AROW + colsel * 8) * 2);

    float acc[2][8][4];
#pragma unroll
    for (int i = 0; i < 2; i++)
#pragma unroll
        for (int j = 0; j < 8; j++)
#pragma unroll
            for (int q = 0; q < 4; q++) acc[i][j][q] = 0.0f;

    // Prologue: stage 0
    load_chunk(sb, Ah, Al, sA, nA, Bh, Bl, sB, nB, tid);
    cpa_commit();

#pragma unroll 1
    for (int c = 0; c < CHUNKS; c++) {
        if (c + 1 < CHUNKS) {
            load_chunk(sb + ((c + 1) & 1) * STAGE_BYTES,
                       Ah + (c + 1) * 64, Al + (c + 1) * 64, sA, nA,
                       Bh + (c + 1) * 64, Bl + (c + 1) * 64, sB, nB, tid);
            cpa_commit();
            cpa_wait<1>();
        } else {
            cpa_wait<0>();
        }
        __syncthreads();

        const uint32_t s = sb + (c & 1) * STAGE_BYTES;
#pragma unroll
        for (int kk = 0; kk < 4; kk++) {
            const uint32_t kb = (uint32_t)kk * 32;   // 16 bf16 = 32 B per k16 step
            uint32_t aH[2][4], aL[2][4], bH[4][4], bL[4][4];
#pragma unroll
            for (int im = 0; im < 2; im++) {
                ldsm4(aH[im], s + 0 * MAT_BYTES + aoff[im] + kb);
                ldsm4(aL[im], s + 1 * MAT_BYTES + aoff[im] + kb);
            }
#pragma unroll
            for (int jn = 0; jn < 4; jn++) {
                ldsm4(bH[jn], s + 2 * MAT_BYTES + boff[jn] + kb);
                ldsm4(bL[jn], s + 3 * MAT_BYTES + boff[jn] + kb);
            }
            // x4 on an n16 x k16 region: regs {0,2} = n-tile 2*jn, {1,3} = 2*jn+1
#pragma unroll
            for (int im = 0; im < 2; im++) {
#pragma unroll
                for (int jn = 0; jn < 4; jn++) {
                    mma16816(acc[im][2 * jn],     aH[im], bH[jn][0], bH[jn][2]);
                    mma16816(acc[im][2 * jn + 1], aH[im], bH[jn][1], bH[jn][3]);
                    mma16816(acc[im][2 * jn],     aH[im], bL[jn][0], bL[jn][2]);
                    mma16816(acc[im][2 * jn + 1], aH[im], bL[jn][1], bL[jn][3]);
                    mma16816(acc[im][2 * jn],     aL[im], bH[jn][0], bH[jn][2]);
                    mma16816(acc[im][2 * jn + 1], aL[im], bH[jn][1], bH[jn][3]);
                }
            }
        }
        __syncthreads();
    }

    // Epilogue: c frag lane mapping — l = 4g+t: rows g, g+8; cols 2t, 2t+1
    const int g = lane >> 2;
    const int t2 = (lane & 3) * 2;
#pragma unroll
    for (int im = 0; im < 2; im++) {
        int r0 = warp_m * 32 + im * 16 + g;
#pragma unroll
        for (int j = 0; j < 8; j++) {
            int cc = warp_n * 64 + j * 8 + t2;
            float* p0 = Co + (size_t)r0 * sC + cc;
            if (r0 < nrow) {
                if (cc < ncol)     p0[0] = acc[im][j][0];
                if (cc + 1 < ncol) p0[1] = acc[im][j][1];
            }
            if (r0 + 8 < nrow) {
                float* p1 = p0 + 8 * sC;
                if (cc < ncol)     p1[0] = acc[im][j][2];
                if (cc + 1 < ncol) p1[1] = acc[im][j][3];
            }
        }
    }
}

// ---------------------------------------------------------------------------
// GEMM1: scores[b,y,l] = U_w[y,:] . x[b,l,:]  (M=Y, N=L, K=D)
// ---------------------------------------------------------------------------
__global__ __launch_bounds__(256, 1)
void gemm1_tc(float* __restrict__ scores) {
    const int b  = blockIdx.z;
    const int m0 = blockIdx.y * 128;
    const int n0 = blockIdx.x * 128;
    int nA = min(Y - m0, 128);
    int nB = min(L - n0, 128);
    gemm_core<D / 64>(
        g_U_hi + (size_t)m0 * D, g_U_lo + (size_t)m0 * D, D, nA,
        g_x_hi + ((size_t)b * L + n0) * D, g_x_lo + ((size_t)b * L + n0) * D, D, nB,
        scores + ((size_t)b * Y + m0) * L + n0, L, nA, nB);
}

// ---------------------------------------------------------------------------
// GEMM2: m[b,y,d] = alpha[b,y,:] . xT[b,d,:]  (M=Y, N=D, K=LP)
// ---------------------------------------------------------------------------
__global__ __launch_bounds__(256, 1)
void gemm2_tc(float* __restrict__ mout) {
    const int b  = blockIdx.z;
    const int m0 = blockIdx.y * 128;
    const int n0 = blockIdx.x * 128;
    int nA = min(Y - m0, 128);
    gemm_core<LP / 64>(
        g_a_hi + ((size_t)b * Y + m0) * LP, g_a_lo + ((size_t)b * Y + m0) * LP, LP, nA,
        g_xT_hi + ((size_t)b * D + n0) * LP, g_xT_lo + ((size_t)b * D + n0) * LP, LP, 128,
        mout + ((size_t)b * Y + m0) * D + n0, D, nA, 128);
}

// ---------------------------------------------------------------------------
// Splitters / transpose
// ---------------------------------------------------------------------------
__global__ __launch_bounds__(256)
void split_u(const float* __restrict__ src) {
    size_t n = (size_t)Y * D;
    for (size_t i = (size_t)blockIdx.x * 256 + threadIdx.x; i < n; i += (size_t)gridDim.x * 256) {
        float v = src[i];
        __nv_bfloat16 h = __float2bfloat16(v);
        float r = v - __bfloat162float(h);
        g_U_hi[i] = h;
        g_U_lo[i] = __float2bfloat16(r);
    }
}

__global__ __launch_bounds__(256)
void split_x(const float* __restrict__ src) {
    size_t n = (size_t)B * L * D;
    for (size_t i = (size_t)blockIdx.x * 256 + threadIdx.x; i < n; i += (size_t)gridDim.x * 256) {
        float v = src[i];
        __nv_bfloat16 h = __float2bfloat16(v);
        float r = v - __bfloat162float(h);
        g_x_hi[i] = h;
        g_x_lo[i] = __float2bfloat16(r);
    }
}

__global__ __launch_bounds__(256)
void transpose_x(const float* __restrict__ x) {
    __shared__ float t[32][33];
    const int b  = blockIdx.z;
    const int l0 = blockIdx.x * 32;
    const int d0 = blockIdx.y * 32;
    const float* xb = x + (size_t)b * L * D;
    const int tx = threadIdx.x & 31;
    const int ty = threadIdx.x >> 5;   // 0..7
#pragma unroll
    for (int i = ty; i < 32; i += 8) {
        int l = l0 + i;
        t[i][tx] = (l < L) ? xb[(size_t)l * D + d0 + tx] : 0.0f;
    }
    __syncthreads();
#pragma unroll
    for (int i = ty; i < 32; i += 8) {
        int d = d0 + i;
        int l = l0 + tx;
        float v = t[tx][i];
        __nv_bfloat16 h = __float2bfloat16(v);
        float r = v - __bfloat162float(h);
        size_t o = ((size_t)b * D + d) * LP + l;
        g_xT_hi[o] = h;
        g_xT_lo[o] = __float2bfloat16(r);
    }
}

// ---------------------------------------------------------------------------
// Softmax over L per row (in place, fp32) + bf16 hi/lo split output (padded)
// ---------------------------------------------------------------------------
__global__ __launch_bounds__(256)
void softmax_rows(float* __restrict__ a) {
    const int row = blockIdx.x;
    float* p = a + (size_t)row * L;
    const int tid = threadIdx.x;

    float vals[10];
    int cnt = 0;
    float mx = -INFINITY;
    for (int i = tid; i < L; i += 256) {
        float v = p[i];
        vals[cnt++] = v;
        mx = fmaxf(mx, v);
    }
    __shared__ float red[256];
    red[tid] = mx; __syncthreads();
    for (int s = 128; s > 0; s >>= 1) {
        if (tid < s) red[tid] = fmaxf(red[tid], red[tid + s]);
        __syncthreads();
    }
    mx = red[0];
    __syncthreads();

    float sum = 0.f;
    for (int c = 0; c < cnt; c++) {
        vals[c] = expf(vals[c] - mx);
        sum += vals[c];
    }
    red[tid] = sum; __syncthreads();
    for (int s = 128; s > 0; s >>= 1) {
        if (tid < s) red[tid] += red[tid + s];
        __syncthreads();
    }
    float inv = 1.0f / red[0];

    size_t ob = (size_t)row * LP;
    cnt = 0;
    for (int i = tid; i < L; i += 256) {
        float v = vals[cnt++] * inv;
        p[i] = v;
        __nv_bfloat16 h = __float2bfloat16(v);
        float r = v - __bfloat162float(h);
        g_a_hi[ob + i] = h;
        g_a_lo[ob + i] = __float2bfloat16(r);
    }
    __nv_bfloat16 z = __float2bfloat16(0.0f);
    for (int i = L + tid; i < LP; i += 256) {
        g_a_hi[ob + i] = z;
        g_a_lo[ob + i] = z;
    }
}

// ---------------------------------------------------------------------------
// Final dot + BCE term per row; loss reduce
// ---------------------------------------------------------------------------
__global__ __launch_bounds__(128)
void final_kernel(const float* __restrict__ mrr,
                  const float* __restrict__ fw,
                  const float* __restrict__ fb,
                  const float* __restrict__ target,
                  float* __restrict__ out_y) {
    const int r = blockIdx.x;
    const int i = r % Y;
    const float* mp = mrr + (size_t)r * D;
    const float* wp = fw + (size_t)i * D;
    const int tid = threadIdx.x;

    float s = 0.f;
    for (int d = tid; d < D; d += 128) s = fmaf(wp[d], mp[d], s);
#pragma unroll
    for (int off = 16; off > 0; off >>= 1) s += __shfl_down_sync(0xffffffffu, s, off);

    __shared__ float sh[4];
    if ((tid & 31) == 0) sh[tid >> 5] = s;
    __syncthreads();
    if (tid == 0) {
        float yv = sh[0] + sh[1] + sh[2] + sh[3] + fb[i];
        out_y[r] = yv;
        float t = target[r];
        g_bce[r] = fmaxf(yv, 0.f) - yv * t + log1pf(expf(-fabsf(yv)));
    }
}

__global__ __launch_bounds__(256)
void loss_reduce(float* __restrict__ out_loss) {
    __shared__ double sh[256];
    double s = 0.0;
    for (int i = threadIdx.x; i < B * Y; i += 256) s += (double)g_bce[i];
    sh[threadIdx.x] = s;
    __syncthreads();
    for (int st = 128; st > 0; st >>= 1) {
        if (threadIdx.x < st) sh[threadIdx.x] += sh[threadIdx.x + st];
        __syncthreads();
    }
    if (threadIdx.x == 0) out_loss[0] = (float)(sh[0] / (double)(B * Y));
}

// ---------------------------------------------------------------------------
// Launch. Output layout: [y (B*Y), loss (1), alpha (B*Y*L), m (B*Y*D)]
// ---------------------------------------------------------------------------
extern "C" void kernel_launch(void* const* d_in, const int* in_sizes, int n_in,
                              void* d_out, int out_size) {
    const float* x      = (const float*)d_in[0];
    const float* target = (const float*)d_in[1];
    // d_in[2] = text_inputs (unused)
    const float* Uw     = (const float*)d_in[3];
    const float* fw     = (const float*)d_in[4];
    const float* fb     = (const float*)d_in[5];

    float* out       = (float*)d_out;
    float* out_y     = out;
    float* out_loss  = out + (size_t)B * Y;
    float* out_alpha = out_loss + 1;
    float* out_m     = out_alpha + (size_t)B * Y * L;

    static int attr_done = 0;
    cudaFuncSetAttribute(gemm1_tc, cudaFuncAttributeMaxDynamicSharedMemorySize, SMEM_BYTES);
    cudaFuncSetAttribute(gemm2_tc, cudaFuncAttributeMaxDynamicSharedMemorySize, SMEM_BYTES);
    (void)attr_done;

    split_u<<<2048, 256>>>(Uw);
    split_x<<<8192, 256>>>(x);
    transpose_x<<<dim3(LP / 32, D / 32, B), 256>>>(x);

    gemm1_tc<<<dim3((L + 127) / 128, (Y + 127) / 128, B), 256, SMEM_BYTES>>>(out_alpha);

    softmax_rows<<<B * Y, 256>>>(out_alpha);

    gemm2_tc<<<dim3(D / 128, (Y + 127) / 128, B), 256, SMEM_BYTES>>>(out_m);

    final_kernel<<<B * Y, 128>>>(out_m, fw, fb, target, out_y);
    loss_reduce<<<1, 256>>>(out_loss);
}

// round 5
// speedup vs baseline: 2.1610x; 1.0417x over previous
#include <cuda_runtime.h>
#include <cuda_bf16.h>
#include <math.h>
#include <stdint.h>

// Problem constants
#define B 8
#define L 2500
#define D 512
#define Y 8921
#define LP 2560            // L padded (K of GEMM2)

// GEMM geometry: CTA tile 128(M) x 256(N), K-chunk 32, 16 warps (32x64 each)
#define KC 32
#define ROWB 64                       // 32 bf16 per row = 64 bytes
#define A_MAT 8192                    // 128 x 64B
#define B_MAT 16384                   // 256 x 64B
#define STAGE_BYTES 49152             // Ah + Al + Bh + Bl
#define NSTAGE 3
#define SMEM_BYTES (NSTAGE * STAGE_BYTES)   // 147456

// ---------------------------------------------------------------------------
// Device scratch (no cudaMalloc allowed)
// ---------------------------------------------------------------------------
__device__ __align__(16) __nv_bfloat16 g_x_hi[(size_t)B * L * D];
__device__ __align__(16) __nv_bfloat16 g_x_lo[(size_t)B * L * D];
__device__ __align__(16) __nv_bfloat16 g_xT_hi[(size_t)B * D * LP];
__device__ __align__(16) __nv_bfloat16 g_xT_lo[(size_t)B * D * LP];
__device__ __align__(16) __nv_bfloat16 g_U_hi[(size_t)Y * D];
__device__ __align__(16) __nv_bfloat16 g_U_lo[(size_t)Y * D];
__device__ __align__(16) __nv_bfloat16 g_a_hi[(size_t)B * Y * LP];
__device__ __align__(16) __nv_bfloat16 g_a_lo[(size_t)B * Y * LP];
__device__ float g_bce[B * Y];

// ---------------------------------------------------------------------------
// PTX helpers (base sm_103-legal)
// ---------------------------------------------------------------------------
__device__ __forceinline__ uint32_t smem_u32(const void* p) {
    uint32_t a;
    asm("{ .reg .u64 t; cvta.to.shared.u64 t, %1; cvt.u32.u64 %0, t; }"
        : "=r"(a) : "l"(p));
    return a;
}
__device__ __forceinline__ void cpa16(uint32_t dst, const void* src, int szbytes) {
    asm volatile("cp.async.cg.shared.global [%0], [%1], 16, %2;"
                 :: "r"(dst), "l"(src), "r"(szbytes) : "memory");
}
__device__ __forceinline__ void cpa_commit() {
    asm volatile("cp.async.commit_group;" ::: "memory");
}
template <int N>
__device__ __forceinline__ void cpa_wait() {
    asm volatile("cp.async.wait_group %0;" :: "n"(N) : "memory");
}
__device__ __forceinline__ void ldsm4(uint32_t* r, uint32_t addr) {
    asm volatile("ldmatrix.sync.aligned.m8n8.x4.shared.b16 {%0,%1,%2,%3}, [%4];"
                 : "=r"(r[0]), "=r"(r[1]), "=r"(r[2]), "=r"(r[3]) : "r"(addr));
}
__device__ __forceinline__ void mma16816(float* c, const uint32_t* a,
                                         uint32_t b0, uint32_t b1) {
    asm volatile(
        "mma.sync.aligned.m16n8k16.row.col.f32.bf16.bf16.f32 "
        "{%0,%1,%2,%3}, {%4,%5,%6,%7}, {%8,%9}, {%0,%1,%2,%3};"
        : "+f"(c[0]), "+f"(c[1]), "+f"(c[2]), "+f"(c[3])
        : "r"(a[0]), "r"(a[1]), "r"(a[2]), "r"(a[3]), "r"(b0), "r"(b1));
}

// XOR swizzle for 64B rows: (row, 16B-chunk c in 0..3)
__device__ __forceinline__ uint32_t swz(int r, int c) {
    return (uint32_t)(r * 64 + ((c ^ ((r >> 1) & 3)) << 4));
}

// ---------------------------------------------------------------------------
// Chunk loader: Ah/Al (128 x 32 bf16) + Bh/Bl (256 x 32 bf16), cp.async 16B.
// ---------------------------------------------------------------------------
__device__ __forceinline__ void load_chunk(uint32_t st, int kt,
        const __nv_bfloat16* __restrict__ Ah, const __nv_bfloat16* __restrict__ Al,
        size_t sA, int nA,
        const __nv_bfloat16* __restrict__ Bh, const __nv_bfloat16* __restrict__ Bl,
        size_t sB, int nB, int tid) {
    {
        int r = tid >> 2, c = tid & 3;
        uint32_t o = swz(r, c);
        bool ok = r < nA;
        size_t so = ok ? ((size_t)r * sA + kt + c * 8) : 0;
        cpa16(st + o,          Ah + so, ok ? 16 : 0);
        cpa16(st + A_MAT + o,  Al + so, ok ? 16 : 0);
    }
#pragma unroll
    for (int it = 0; it < 2; it++) {
        int idx = tid + it * 512;
        int r = idx >> 2, c = idx & 3;
        uint32_t o = swz(r, c);
        bool ok = r < nB;
        size_t so = ok ? ((size_t)r * sB + kt + c * 8) : 0;
        cpa16(st + 2 * A_MAT + o,         Bh + so, ok ? 16 : 0);
        cpa16(st + 2 * A_MAT + B_MAT + o, Bl + so, ok ? 16 : 0);
    }
}

// ---------------------------------------------------------------------------
// Core GEMM: C[m<=128, n<=256] = sum_k (Ah+Al)[m,k]*(Bh+Bl)[n,k] (drop lo*lo)
// 512 threads, 16 warps 4(M) x 4(N), warp tile 32x64, m16n8k16 bf16.
// ---------------------------------------------------------------------------
template <int CHUNKS>
__device__ __forceinline__ void gemm_core(
    const __nv_bfloat16* __restrict__ Ah, const __nv_bfloat16* __restrict__ Al,
    size_t sA, int nA,
    const __nv_bfloat16* __restrict__ Bh, const __nv_bfloat16* __restrict__ Bl,
    size_t sB, int nB,
    float* __restrict__ Co, size_t sC, int nrow, int ncol)
{
    extern __shared__ __align__(128) char smem[];
    const uint32_t sb = smem_u32(smem);
    const int tid = threadIdx.x;
    const int lane = tid & 31;
    const int wid = tid >> 5;
    const int warp_m = wid >> 2;     // 0..3 -> 32-row slabs
    const int warp_n = wid & 3;      // 0..3 -> 64-col slabs

    const int rowsel = (lane & 7) + ((lane >> 3) & 1) * 8;
    const int colsel = (lane >> 4) & 1;

    // Precomputed per-lane ldmatrix row bases + swizzle keys
    int ar64[2], asw[2], br64[4], bsw[4];
#pragma unroll
    for (int im = 0; im < 2; im++) {
        int r = warp_m * 32 + im * 16 + rowsel;
        ar64[im] = r * 64;
        asw[im] = (r >> 1) & 3;
    }
#pragma unroll
    for (int jn = 0; jn < 4; jn++) {
        int r = warp_n * 64 + jn * 16 + rowsel;
        br64[jn] = r * 64;
        bsw[jn] = (r >> 1) & 3;
    }

    float acc[2][8][4];
#pragma unroll
    for (int i = 0; i < 2; i++)
#pragma unroll
        for (int j = 0; j < 8; j++)
#pragma unroll
            for (int q = 0; q < 4; q++) acc[i][j][q] = 0.0f;

    // Prologue: issue stages 0..NSTAGE-2
#pragma unroll
    for (int p = 0; p < NSTAGE - 1; p++) {
        load_chunk(sb + p * STAGE_BYTES, p * KC, Ah, Al, sA, nA, Bh, Bl, sB, nB, tid);
        cpa_commit();
    }

#pragma unroll 1
    for (int c = 0; c < CHUNKS; c++) {
        if (c + 2 < CHUNKS) {
            cpa_wait<1>();
            __syncthreads();
            load_chunk(sb + ((c + 2) % NSTAGE) * STAGE_BYTES, (c + 2) * KC,
                       Ah, Al, sA, nA, Bh, Bl, sB, nB, tid);
            cpa_commit();
        } else if (c + 2 == CHUNKS) {
            cpa_wait<1>();
            __syncthreads();
        } else {
            cpa_wait<0>();
            __syncthreads();
        }

        const uint32_t s = sb + (c % NSTAGE) * STAGE_BYTES;
#pragma unroll
        for (int kk = 0; kk < 2; kk++) {
            const int ch = kk * 2 + colsel;
            uint32_t aH[2][4], aL[2][4];
#pragma unroll
            for (int im = 0; im < 2; im++) {
                uint32_t off = (uint32_t)ar64[im] + (uint32_t)((ch ^ asw[im]) << 4);
                ldsm4(aH[im], s + off);
                ldsm4(aL[im], s + A_MAT + off);
            }
#pragma unroll
            for (int jn = 0; jn < 4; jn++) {
                uint32_t off = (uint32_t)br64[jn] + (uint32_t)((ch ^ bsw[jn]) << 4);
                uint32_t bH[4], bL[4];
                ldsm4(bH, s + 2 * A_MAT + off);
                ldsm4(bL, s + 2 * A_MAT + B_MAT + off);
#pragma unroll
                for (int im = 0; im < 2; im++) {
                    mma16816(acc[im][2 * jn],     aH[im], bH[0], bH[2]);
                    mma16816(acc[im][2 * jn + 1], aH[im], bH[1], bH[3]);
                    mma16816(acc[im][2 * jn],     aH[im], bL[0], bL[2]);
                    mma16816(acc[im][2 * jn + 1], aH[im], bL[1], bL[3]);
                    mma16816(acc[im][2 * jn],     aL[im], bH[0], bH[2]);
                    mma16816(acc[im][2 * jn + 1], aL[im], bH[1], bH[3]);
                }
            }
        }
        __syncthreads();
    }

    // Epilogue: lane l = 4g+t -> rows g, g+8; cols 2t, 2t+1
    const int g = lane >> 2;
    const int t2 = (lane & 3) * 2;
#pragma unroll
    for (int im = 0; im < 2; im++) {
        int r0 = warp_m * 32 + im * 16 + g;
#pragma unroll
        for (int j = 0; j < 8; j++) {
            int cc = warp_n * 64 + j * 8 + t2;
            float* p0 = Co + (size_t)r0 * sC + cc;
            if (r0 < nrow) {
                if (cc < ncol)     p0[0] = acc[im][j][0];
                if (cc + 1 < ncol) p0[1] = acc[im][j][1];
            }
            if (r0 + 8 < nrow) {
                float* p1 = p0 + 8 * sC;
                if (cc < ncol)     p1[0] = acc[im][j][2];
                if (cc + 1 < ncol) p1[1] = acc[im][j][3];
            }
        }
    }
}

// ---------------------------------------------------------------------------
// GEMM1: scores[b,y,l] = U_w[y,:] . x[b,l,:]  (M=Y, N=L, K=D)
// ---------------------------------------------------------------------------
__global__ __launch_bounds__(512, 1)
void gemm1_tc(float* __restrict__ scores) {
    const int b  = blockIdx.z;
    const int m0 = blockIdx.y * 128;
    const int n0 = blockIdx.x * 256;
    int nA = min(Y - m0, 128);
    int nB = min(L - n0, 256);
    gemm_core<D / KC>(
        g_U_hi + (size_t)m0 * D, g_U_lo + (size_t)m0 * D, D, nA,
        g_x_hi + ((size_t)b * L + n0) * D, g_x_lo + ((size_t)b * L + n0) * D, D, nB,
        scores + ((size_t)b * Y + m0) * L + n0, L, nA, nB);
}

// ---------------------------------------------------------------------------
// GEMM2: m[b,y,d] = alpha[b,y,:] . xT[b,d,:]  (M=Y, N=D, K=LP)
// ---------------------------------------------------------------------------
__global__ __launch_bounds__(512, 1)
void gemm2_tc(float* __restrict__ mout) {
    const int b  = blockIdx.z;
    const int m0 = blockIdx.y * 128;
    const int n0 = blockIdx.x * 256;
    int nA = min(Y - m0, 128);
    gemm_core<LP / KC>(
        g_a_hi + ((size_t)b * Y + m0) * LP, g_a_lo + ((size_t)b * Y + m0) * LP, LP, nA,
        g_xT_hi + ((size_t)b * D + n0) * LP, g_xT_lo + ((size_t)b * D + n0) * LP, LP, 256,
        mout + ((size_t)b * Y + m0) * D + n0, D, nA, 256);
}

// ---------------------------------------------------------------------------
// Splitters / transpose
// ---------------------------------------------------------------------------
__global__ __launch_bounds__(256)
void split_u(const float* __restrict__ src) {
    size_t n = (size_t)Y * D;
    for (size_t i = (size_t)blockIdx.x * 256 + threadIdx.x; i < n; i += (size_t)gridDim.x * 256) {
        float v = src[i];
        __nv_bfloat16 h = __float2bfloat16(v);
        float r = v - __bfloat162float(h);
        g_U_hi[i] = h;
        g_U_lo[i] = __float2bfloat16(r);
    }
}

__global__ __launch_bounds__(256)
void split_x(const float* __restrict__ src) {
    size_t n = (size_t)B * L * D;
    for (size_t i = (size_t)blockIdx.x * 256 + threadIdx.x; i < n; i += (size_t)gridDim.x * 256) {
        float v = src[i];
        __nv_bfloat16 h = __float2bfloat16(v);
        float r = v - __bfloat162float(h);
        g_x_hi[i] = h;
        g_x_lo[i] = __float2bfloat16(r);
    }
}

__global__ __launch_bounds__(256)
void transpose_x(const float* __restrict__ x) {
    __shared__ float t[32][33];
    const int b  = blockIdx.z;
    const int l0 = blockIdx.x * 32;
    const int d0 = blockIdx.y * 32;
    const float* xb = x + (size_t)b * L * D;
    const int tx = threadIdx.x & 31;
    const int ty = threadIdx.x >> 5;   // 0..7
#pragma unroll
    for (int i = ty; i < 32; i += 8) {
        int l = l0 + i;
        t[i][tx] = (l < L) ? xb[(size_t)l * D + d0 + tx] : 0.0f;
    }
    __syncthreads();
#pragma unroll
    for (int i = ty; i < 32; i += 8) {
        int d = d0 + i;
        int l = l0 + tx;
        float v = t[tx][i];
        __nv_bfloat16 h = __float2bfloat16(v);
        float r = v - __bfloat162float(h);
        size_t o = ((size_t)b * D + d) * LP + l;
        g_xT_hi[o] = h;
        g_xT_lo[o] = __float2bfloat16(r);
    }
}

// ---------------------------------------------------------------------------
// Softmax over L per row (in place, fp32) + bf16 hi/lo split output (padded)
// ---------------------------------------------------------------------------
__global__ __launch_bounds__(256)
void softmax_rows(float* __restrict__ a) {
    const int row = blockIdx.x;
    float* p = a + (size_t)row * L;
    const int tid = threadIdx.x;

    float vals[10];
    int cnt = 0;
    float mx = -INFINITY;
    for (int i = tid; i < L; i += 256) {
        float v = p[i];
        vals[cnt++] = v;
        mx = fmaxf(mx, v);
    }
    __shared__ float red[256];
    red[tid] = mx; __syncthreads();
    for (int s = 128; s > 0; s >>= 1) {
        if (tid < s) red[tid] = fmaxf(red[tid], red[tid + s]);
        __syncthreads();
    }
    mx = red[0];
    __syncthreads();

    float sum = 0.f;
    for (int c = 0; c < cnt; c++) {
        vals[c] = expf(vals[c] - mx);
        sum += vals[c];
    }
    red[tid] = sum; __syncthreads();
    for (int s = 128; s > 0; s >>= 1) {
        if (tid < s) red[tid] += red[tid + s];
        __syncthreads();
    }
    float inv = 1.0f / red[0];

    size_t ob = (size_t)row * LP;
    cnt = 0;
    for (int i = tid; i < L; i += 256) {
        float v = vals[cnt++] * inv;
        p[i] = v;
        __nv_bfloat16 h = __float2bfloat16(v);
        float r = v - __bfloat162float(h);
        g_a_hi[ob + i] = h;
        g_a_lo[ob + i] = __float2bfloat16(r);
    }
    __nv_bfloat16 z = __float2bfloat16(0.0f);
    for (int i = L + tid; i < LP; i += 256) {
        g_a_hi[ob + i] = z;
        g_a_lo[ob + i] = z;
    }
}

// ---------------------------------------------------------------------------
// Final dot + BCE term per row; loss reduce
// ---------------------------------------------------------------------------
__global__ __launch_bounds__(128)
void final_kernel(const float* __restrict__ mrr,
                  const float* __restrict__ fw,
                  const float* __restrict__ fb,
                  const float* __restrict__ target,
                  float* __restrict__ out_y) {
    const int r = blockIdx.x;
    const int i = r % Y;
    const float* mp = mrr + (size_t)r * D;
    const float* wp = fw + (size_t)i * D;
    const int tid = threadIdx.x;

    float s = 0.f;
    for (int d = tid; d < D; d += 128) s = fmaf(wp[d], mp[d], s);
#pragma unroll
    for (int off = 16; off > 0; off >>= 1) s += __shfl_down_sync(0xffffffffu, s, off);

    __shared__ float sh[4];
    if ((tid & 31) == 0) sh[tid >> 5] = s;
    __syncthreads();
    if (tid == 0) {
        float yv = sh[0] + sh[1] + sh[2] + sh[3] + fb[i];
        out_y[r] = yv;
        float t = target[r];
        g_bce[r] = fmaxf(yv, 0.f) - yv * t + log1pf(expf(-fabsf(yv)));
    }
}

__global__ __launch_bounds__(256)
void loss_reduce(float* __restrict__ out_loss) {
    __shared__ double sh[256];
    double s = 0.0;
    for (int i = threadIdx.x; i < B * Y; i += 256) s += (double)g_bce[i];
    sh[threadIdx.x] = s;
    __syncthreads();
    for (int st = 128; st > 0; st >>= 1) {
        if (threadIdx.x < st) sh[threadIdx.x] += sh[threadIdx.x + st];
        __syncthreads();
    }
    if (threadIdx.x == 0) out_loss[0] = (float)(sh[0] / (double)(B * Y));
}

// ---------------------------------------------------------------------------
// Launch. Output layout: [y (B*Y), loss (1), alpha (B*Y*L), m (B*Y*D)]
// ---------------------------------------------------------------------------
extern "C" void kernel_launch(void* const* d_in, const int* in_sizes, int n_in,
                              void* d_out, int out_size) {
    const float* x      = (const float*)d_in[0];
    const float* target = (const float*)d_in[1];
    // d_in[2] = text_inputs (unused)
    const float* Uw     = (const float*)d_in[3];
    const float* fw     = (const float*)d_in[4];
    const float* fb     = (const float*)d_in[5];

    float* out       = (float*)d_out;
    float* out_y     = out;
    float* out_loss  = out + (size_t)B * Y;
    float* out_alpha = out_loss + 1;
    float* out_m     = out_alpha + (size_t)B * Y * L;

    cudaFuncSetAttribute(gemm1_tc, cudaFuncAttributeMaxDynamicSharedMemorySize, SMEM_BYTES);
    cudaFuncSetAttribute(gemm2_tc, cudaFuncAttributeMaxDynamicSharedMemorySize, SMEM_BYTES);

    split_u<<<2048, 256>>>(Uw);
    split_x<<<8192, 256>>>(x);
    transpose_x<<<dim3(LP / 32, D / 32, B), 256>>>(x);

    gemm1_tc<<<dim3((L + 255) / 256, (Y + 127) / 128, B), 512, SMEM_BYTES>>>(out_alpha);

    softmax_rows<<<B * Y, 256>>>(out_alpha);

    gemm2_tc<<<dim3(D / 256, (Y + 127) / 128, B), 512, SMEM_BYTES>>>(out_m);

    final_kernel<<<B * Y, 128>>>(out_m, fw, fb, target, out_y);
    loss_reduce<<<1, 256>>>(out_loss);
}

// round 6
// speedup vs baseline: 2.3426x; 1.0841x over previous
#include <cuda_runtime.h>
#include <cuda_bf16.h>
#include <math.h>
#include <stdint.h>

// Problem constants
#define B 8
#define L 2500
#define D 512
#define Y 8921
#define LP 2560            // L padded (K of GEMM2)

// GEMM geometry: CTA tile 128(M) x 256(N), K-chunk 64, 16 warps (32x64 each)
#define KC 64
#define AH_OFF 0
#define AL_OFF 16384
#define BH_OFF 32768
#define BL_OFF 65536
#define STAGE_BYTES 98304            // Ah(16K)+Al(16K)+Bh(32K)+Bl(32K)
#define SMEM_BYTES (2 * STAGE_BYTES) // 196608, 2-stage ring

// ---------------------------------------------------------------------------
// Device scratch (no cudaMalloc allowed)
// ---------------------------------------------------------------------------
__device__ __align__(16) __nv_bfloat16 g_x_hi[(size_t)B * L * D];
__device__ __align__(16) __nv_bfloat16 g_x_lo[(size_t)B * L * D];
__device__ __align__(16) __nv_bfloat16 g_xT_hi[(size_t)B * D * LP];
__device__ __align__(16) __nv_bfloat16 g_xT_lo[(size_t)B * D * LP];
__device__ __align__(16) __nv_bfloat16 g_U_hi[(size_t)Y * D];
__device__ __align__(16) __nv_bfloat16 g_U_lo[(size_t)Y * D];
__device__ __align__(16) __nv_bfloat16 g_a_hi[(size_t)B * Y * LP];
__device__ __align__(16) __nv_bfloat16 g_a_lo[(size_t)B * Y * LP];
__device__ float g_bce[B * Y];

// ---------------------------------------------------------------------------
// PTX helpers (base sm_103-legal)
// ---------------------------------------------------------------------------
__device__ __forceinline__ uint32_t smem_u32(const void* p) {
    uint32_t a;
    asm("{ .reg .u64 t; cvta.to.shared.u64 t, %1; cvt.u32.u64 %0, t; }"
        : "=r"(a) : "l"(p));
    return a;
}
__device__ __forceinline__ void cpa16(uint32_t dst, const void* src, int szbytes) {
    asm volatile("cp.async.cg.shared.global [%0], [%1], 16, %2;"
                 :: "r"(dst), "l"(src), "r"(szbytes) : "memory");
}
__device__ __forceinline__ void cpa_commit() {
    asm volatile("cp.async.commit_group;" ::: "memory");
}
template <int N>
__device__ __forceinline__ void cpa_wait() {
    asm volatile("cp.async.wait_group %0;" :: "n"(N) : "memory");
}
__device__ __forceinline__ void ldsm4(uint32_t* r, uint32_t addr) {
    asm volatile("ldmatrix.sync.aligned.m8n8.x4.shared.b16 {%0,%1,%2,%3}, [%4];"
                 : "=r"(r[0]), "=r"(r[1]), "=r"(r[2]), "=r"(r[3]) : "r"(addr));
}
__device__ __forceinline__ void mma16816(float* c, const uint32_t* a,
                                         uint32_t b0, uint32_t b1) {
    asm volatile(
        "mma.sync.aligned.m16n8k16.row.col.f32.bf16.bf16.f32 "
        "{%0,%1,%2,%3}, {%4,%5,%6,%7}, {%8,%9}, {%0,%1,%2,%3};"
        : "+f"(c[0]), "+f"(c[1]), "+f"(c[2]), "+f"(c[3])
        : "r"(a[0]), "r"(a[1]), "r"(a[2]), "r"(a[3]), "r"(b0), "r"(b1));
}

// 128B-row XOR swizzle: row r, 16B-chunk c (0..7)
__device__ __forceinline__ uint32_t swz128(int r, int c) {
    return (uint32_t)(r * 128 + ((c ^ (r & 7)) << 4));
}

// ---------------------------------------------------------------------------
// Chunk loader: Ah/Al (128 x 64 bf16) + Bh/Bl (256 x 64 bf16), cp.async 16B.
// 512 threads, 12 cp.async per thread.
// ---------------------------------------------------------------------------
__device__ __forceinline__ void load_chunk(uint32_t st, int kt,
        const __nv_bfloat16* __restrict__ Ah, const __nv_bfloat16* __restrict__ Al,
        size_t sA, int nA,
        const __nv_bfloat16* __restrict__ Bh, const __nv_bfloat16* __restrict__ Bl,
        size_t sB, int nB, int tid) {
#pragma unroll
    for (int it = 0; it < 2; it++) {
        int idx = tid + it * 512;
        int r = idx >> 3, c = idx & 7;
        uint32_t o = swz128(r, c);
        bool ok = r < nA;
        size_t so = ok ? ((size_t)r * sA + kt + c * 8) : 0;
        cpa16(st + AH_OFF + o, Ah + so, ok ? 16 : 0);
        cpa16(st + AL_OFF + o, Al + so, ok ? 16 : 0);
    }
#pragma unroll
    for (int it = 0; it < 4; it++) {
        int idx = tid + it * 512;
        int r = idx >> 3, c = idx & 7;
        uint32_t o = swz128(r, c);
        bool ok = r < nB;
        size_t so = ok ? ((size_t)r * sB + kt + c * 8) : 0;
        cpa16(st + BH_OFF + o, Bh + so, ok ? 16 : 0);
        cpa16(st + BL_OFF + o, Bl + so, ok ? 16 : 0);
    }
}

// ---------------------------------------------------------------------------
// Core GEMM: C[m<=128, n<=256] = sum_k (Ah+Al)[m,k]*(Bh+Bl)[n,k] (drop lo*lo)
// 512 threads, 16 warps 4(M) x 4(N), warp tile 32x64, m16n8k16 bf16.
// B fragments register-double-buffered across jn; A frags reloaded per kk.
// ---------------------------------------------------------------------------
template <int CHUNKS>
__device__ __forceinline__ void gemm_core(
    const __nv_bfloat16* __restrict__ Ah, const __nv_bfloat16* __restrict__ Al,
    size_t sA, int nA,
    const __nv_bfloat16* __restrict__ Bh, const __nv_bfloat16* __restrict__ Bl,
    size_t sB, int nB,
    float* __restrict__ Co, size_t sC, int nrow, int ncol)
{
    extern __shared__ __align__(128) char smem[];
    const uint32_t sb = smem_u32(smem);
    const int tid = threadIdx.x;
    const int lane = tid & 31;
    const int wid = tid >> 5;
    const int warp_m = wid >> 2;     // 0..3 -> 32-row slabs
    const int warp_n = wid & 3;      // 0..3 -> 64-col slabs

    const int rowsel = (lane & 7) + ((lane >> 3) & 1) * 8;
    const int colsel = (lane >> 4) & 1;

    // Per-lane row bases and swizzle keys
    int arb[2], arx[2], brb[4], brx[4];
#pragma unroll
    for (int im = 0; im < 2; im++) {
        int r = warp_m * 32 + im * 16 + rowsel;
        arb[im] = r * 128; arx[im] = r & 7;
    }
#pragma unroll
    for (int jn = 0; jn < 4; jn++) {
        int r = warp_n * 64 + jn * 16 + rowsel;
        brb[jn] = r * 128; brx[jn] = r & 7;
    }

    float acc[2][8][4];
#pragma unroll
    for (int i = 0; i < 2; i++)
#pragma unroll
        for (int j = 0; j < 8; j++)
#pragma unroll
            for (int q = 0; q < 4; q++) acc[i][j][q] = 0.0f;

    // Prologue: fill both ring stages
    load_chunk(sb,               0,  Ah, Al, sA, nA, Bh, Bl, sB, nB, tid);
    cpa_commit();
    if (CHUNKS > 1) {
        load_chunk(sb + STAGE_BYTES, KC, Ah, Al, sA, nA, Bh, Bl, sB, nB, tid);
        cpa_commit();
    }

    uint32_t aH[2][4], aL[2][4];
    uint32_t bHb[2][4], bLb[2][4];

#pragma unroll 1
    for (int c = 0; c < CHUNKS; c++) {
        if (c + 1 < CHUNKS) cpa_wait<1>(); else cpa_wait<0>();
        __syncthreads();

        const uint32_t s = sb + (uint32_t)(c & 1) * STAGE_BYTES;

        // initial fragments: A(kk=0), B(kk=0,jn=0)
#pragma unroll
        for (int im = 0; im < 2; im++) {
            uint32_t off = (uint32_t)arb[im] + (uint32_t)(((colsel) ^ arx[im]) << 4);
            ldsm4(aH[im], s + AH_OFF + off);
            ldsm4(aL[im], s + AL_OFF + off);
        }
        {
            uint32_t off = (uint32_t)brb[0] + (uint32_t)(((colsel) ^ brx[0]) << 4);
            ldsm4(bHb[0], s + BH_OFF + off);
            ldsm4(bLb[0], s + BL_OFF + off);
        }

#pragma unroll
        for (int kk = 0; kk < 4; kk++) {
#pragma unroll
            for (int jn = 0; jn < 4; jn++) {
                const int p = (kk * 4 + jn) & 1;
                // Prefetch next B fragments (register double-buffer)
                if (!(kk == 3 && jn == 3)) {
                    const int nk = (jn == 3) ? kk + 1 : kk;
                    const int njn = (jn == 3) ? 0 : jn + 1;
                    uint32_t off = (uint32_t)brb[njn] +
                        (uint32_t)(((nk * 2 + colsel) ^ brx[njn]) << 4);
                    ldsm4(bHb[p ^ 1], s + BH_OFF + off);
                    ldsm4(bLb[p ^ 1], s + BL_OFF + off);
                }
                // 12 MMAs on current fragments
#pragma unroll
                for (int im = 0; im < 2; im++) {
                    mma16816(acc[im][2 * jn],     aH[im], bHb[p][0], bHb[p][2]);
                    mma16816(acc[im][2 * jn + 1], aH[im], bHb[p][1], bHb[p][3]);
                    mma16816(acc[im][2 * jn],     aH[im], bLb[p][0], bLb[p][2]);
                    mma16816(acc[im][2 * jn + 1], aH[im], bLb[p][1], bLb[p][3]);
                    mma16816(acc[im][2 * jn],     aL[im], bHb[p][0], bHb[p][2]);
                    mma16816(acc[im][2 * jn + 1], aL[im], bHb[p][1], bHb[p][3]);
                }
                // Reload A fragments for next kk after their last use this kk
                if (jn == 3 && kk < 3) {
#pragma unroll
                    for (int im = 0; im < 2; im++) {
                        uint32_t off = (uint32_t)arb[im] +
                            (uint32_t)((((kk + 1) * 2 + colsel) ^ arx[im]) << 4);
                        ldsm4(aH[im], s + AH_OFF + off);
                        ldsm4(aL[im], s + AL_OFF + off);
                    }
                }
            }
        }

        __syncthreads();
        if (c + 2 < CHUNKS) {
            load_chunk(s, (c + 2) * KC, Ah, Al, sA, nA, Bh, Bl, sB, nB, tid);
            cpa_commit();
        }
    }

    // Epilogue: lane l = 4g+t -> rows g, g+8; cols 2t, 2t+1
    const int g = lane >> 2;
    const int t2 = (lane & 3) * 2;
#pragma unroll
    for (int im = 0; im < 2; im++) {
        int r0 = warp_m * 32 + im * 16 + g;
#pragma unroll
        for (int j = 0; j < 8; j++) {
            int cc = warp_n * 64 + j * 8 + t2;
            float* p0 = Co + (size_t)r0 * sC + cc;
            if (r0 < nrow) {
                if (cc < ncol)     p0[0] = acc[im][j][0];
                if (cc + 1 < ncol) p0[1] = acc[im][j][1];
            }
            if (r0 + 8 < nrow) {
                float* p1 = p0 + 8 * sC;
                if (cc < ncol)     p1[0] = acc[im][j][2];
                if (cc + 1 < ncol) p1[1] = acc[im][j][3];
            }
        }
    }
}

// ---------------------------------------------------------------------------
// GEMM1: scores[b,y,l] = U_w[y,:] . x[b,l,:]  (M=Y, N=L, K=D)
// ---------------------------------------------------------------------------
__global__ __launch_bounds__(512, 1)
void gemm1_tc(float* __restrict__ scores) {
    const int b  = blockIdx.z;
    const int m0 = blockIdx.y * 128;
    const int n0 = blockIdx.x * 256;
    int nA = min(Y - m0, 128);
    int nB = min(L - n0, 256);
    gemm_core<D / KC>(
        g_U_hi + (size_t)m0 * D, g_U_lo + (size_t)m0 * D, D, nA,
        g_x_hi + ((size_t)b * L + n0) * D, g_x_lo + ((size_t)b * L + n0) * D, D, nB,
        scores + ((size_t)b * Y + m0) * L + n0, L, nA, nB);
}

// ---------------------------------------------------------------------------
// GEMM2: m[b,y,d] = alpha[b,y,:] . xT[b,d,:]  (M=Y, N=D, K=LP)
// ---------------------------------------------------------------------------
__global__ __launch_bounds__(512, 1)
void gemm2_tc(float* __restrict__ mout) {
    const int b  = blockIdx.z;
    const int m0 = blockIdx.y * 128;
    const int n0 = blockIdx.x * 256;
    int nA = min(Y - m0, 128);
    gemm_core<LP / KC>(
        g_a_hi + ((size_t)b * Y + m0) * LP, g_a_lo + ((size_t)b * Y + m0) * LP, LP, nA,
        g_xT_hi + ((size_t)b * D + n0) * LP, g_xT_lo + ((size_t)b * D + n0) * LP, LP, 256,
        mout + ((size_t)b * Y + m0) * D + n0, D, nA, 256);
}

// ---------------------------------------------------------------------------
// Splitters / transpose
// ---------------------------------------------------------------------------
__global__ __launch_bounds__(256)
void split_u(const float* __restrict__ src) {
    size_t n = (size_t)Y * D;
    for (size_t i = (size_t)blockIdx.x * 256 + threadIdx.x; i < n; i += (size_t)gridDim.x * 256) {
        float v = src[i];
        __nv_bfloat16 h = __float2bfloat16(v);
        float r = v - __bfloat162float(h);
        g_U_hi[i] = h;
        g_U_lo[i] = __float2bfloat16(r);
    }
}

__global__ __launch_bounds__(256)
void split_x(const float* __restrict__ src) {
    size_t n = (size_t)B * L * D;
    for (size_t i = (size_t)blockIdx.x * 256 + threadIdx.x; i < n; i += (size_t)gridDim.x * 256) {
        float v = src[i];
        __nv_bfloat16 h = __float2bfloat16(v);
        float r = v - __bfloat162float(h);
        g_x_hi[i] = h;
        g_x_lo[i] = __float2bfloat16(r);
    }
}

__global__ __launch_bounds__(256)
void transpose_x(const float* __restrict__ x) {
    __shared__ float t[32][33];
    const int b  = blockIdx.z;
    const int l0 = blockIdx.x * 32;
    const int d0 = blockIdx.y * 32;
    const float* xb = x + (size_t)b * L * D;
    const int tx = threadIdx.x & 31;
    const int ty = threadIdx.x >> 5;   // 0..7
#pragma unroll
    for (int i = ty; i < 32; i += 8) {
        int l = l0 + i;
        t[i][tx] = (l < L) ? xb[(size_t)l * D + d0 + tx] : 0.0f;
    }
    __syncthreads();
#pragma unroll
    for (int i = ty; i < 32; i += 8) {
        int d = d0 + i;
        int l = l0 + tx;
        float v = t[tx][i];
        __nv_bfloat16 h = __float2bfloat16(v);
        float r = v - __bfloat162float(h);
        size_t o = ((size_t)b * D + d) * LP + l;
        g_xT_hi[o] = h;
        g_xT_lo[o] = __float2bfloat16(r);
    }
}

// ---------------------------------------------------------------------------
// Softmax over L per row (in place, fp32) + bf16 hi/lo split output (padded)
// ---------------------------------------------------------------------------
__global__ __launch_bounds__(256)
void softmax_rows(float* __restrict__ a) {
    const int row = blockIdx.x;
    float* p = a + (size_t)row * L;
    const int tid = threadIdx.x;

    float vals[10];
    int cnt = 0;
    float mx = -INFINITY;
    for (int i = tid; i < L; i += 256) {
        float v = p[i];
        vals[cnt++] = v;
        mx = fmaxf(mx, v);
    }
    __shared__ float red[256];
    red[tid] = mx; __syncthreads();
    for (int s = 128; s > 0; s >>= 1) {
        if (tid < s) red[tid] = fmaxf(red[tid], red[tid + s]);
        __syncthreads();
    }
    mx = red[0];
    __syncthreads();

    float sum = 0.f;
    for (int c = 0; c < cnt; c++) {
        vals[c] = expf(vals[c] - mx);
        sum += vals[c];
    }
    red[tid] = sum; __syncthreads();
    for (int s = 128; s > 0; s >>= 1) {
        if (tid < s) red[tid] += red[tid + s];
        __syncthreads();
    }
    float inv = 1.0f / red[0];

    size_t ob = (size_t)row * LP;
    cnt = 0;
    for (int i = tid; i < L; i += 256) {
        float v = vals[cnt++] * inv;
        p[i] = v;
        __nv_bfloat16 h = __float2bfloat16(v);
        float r = v - __bfloat162float(h);
        g_a_hi[ob + i] = h;
        g_a_lo[ob + i] = __float2bfloat16(r);
    }
    __nv_bfloat16 z = __float2bfloat16(0.0f);
    for (int i = L + tid; i < LP; i += 256) {
        g_a_hi[ob + i] = z;
        g_a_lo[ob + i] = z;
    }
}

// ---------------------------------------------------------------------------
// Final dot + BCE term per row; loss reduce
// ---------------------------------------------------------------------------
__global__ __launch_bounds__(128)
void final_kernel(const float* __restrict__ mrr,
                  const float* __restrict__ fw,
                  const float* __restrict__ fb,
                  const float* __restrict__ target,
                  float* __restrict__ out_y) {
    const int r = blockIdx.x;
    const int i = r % Y;
    const float* mp = mrr + (size_t)r * D;
    const float* wp = fw + (size_t)i * D;
    const int tid = threadIdx.x;

    float s = 0.f;
    for (int d = tid; d < D; d += 128) s = fmaf(wp[d], mp[d], s);
#pragma unroll
    for (int off = 16; off > 0; off >>= 1) s += __shfl_down_sync(0xffffffffu, s, off);

    __shared__ float sh[4];
    if ((tid & 31) == 0) sh[tid >> 5] = s;
    __syncthreads();
    if (tid == 0) {
        float yv = sh[0] + sh[1] + sh[2] + sh[3] + fb[i];
        out_y[r] = yv;
        float t = target[r];
        g_bce[r] = fmaxf(yv, 0.f) - yv * t + log1pf(expf(-fabsf(yv)));
    }
}

__global__ __launch_bounds__(256)
void loss_reduce(float* __restrict__ out_loss) {
    __shared__ double sh[256];
    double s = 0.0;
    for (int i = threadIdx.x; i < B * Y; i += 256) s += (double)g_bce[i];
    sh[threadIdx.x] = s;
    __syncthreads();
    for (int st = 128; st > 0; st >>= 1) {
        if (threadIdx.x < st) sh[threadIdx.x] += sh[threadIdx.x + st];
        __syncthreads();
    }
    if (threadIdx.x == 0) out_loss[0] = (float)(sh[0] / (double)(B * Y));
}

// ---------------------------------------------------------------------------
// Launch. Output layout: [y (B*Y), loss (1), alpha (B*Y*L), m (B*Y*D)]
// ---------------------------------------------------------------------------
extern "C" void kernel_launch(void* const* d_in, const int* in_sizes, int n_in,
                              void* d_out, int out_size) {
    const float* x      = (const float*)d_in[0];
    const float* target = (const float*)d_in[1];
    // d_in[2] = text_inputs (unused)
    const float* Uw     = (const float*)d_in[3];
    const float* fw     = (const float*)d_in[4];
    const float* fb     = (const float*)d_in[5];

    float* out       = (float*)d_out;
    float* out_y     = out;
    float* out_loss  = out + (size_t)B * Y;
    float* out_alpha = out_loss + 1;
    float* out_m     = out_alpha + (size_t)B * Y * L;

    cudaFuncSetAttribute(gemm1_tc, cudaFuncAttributeMaxDynamicSharedMemorySize, SMEM_BYTES);
    cudaFuncSetAttribute(gemm2_tc, cudaFuncAttributeMaxDynamicSharedMemorySize, SMEM_BYTES);

    split_u<<<2048, 256>>>(Uw);
    split_x<<<8192, 256>>>(x);
    transpose_x<<<dim3(LP / 32, D / 32, B), 256>>>(x);

    gemm1_tc<<<dim3((L + 255) / 256, (Y + 127) / 128, B), 512, SMEM_BYTES>>>(out_alpha);

    softmax_rows<<<B * Y, 256>>>(out_alpha);

    gemm2_tc<<<dim3(D / 256, (Y + 127) / 128, B), 512, SMEM_BYTES>>>(out_m);

    final_kernel<<<B * Y, 128>>>(out_m, fw, fb, target, out_y);
    loss_reduce<<<1, 256>>>(out_loss);
}

// round 7
// speedup vs baseline: 2.4380x; 1.0407x over previous
#include <cuda_runtime.h>
#include <cuda_bf16.h>
#include <math.h>
#include <stdint.h>

// Problem constants
#define B 8
#define L 2500
#define D 512
#define Y 8921
#define LP 2560            // L padded (K of GEMM2)

// GEMM geometry: CTA tile 128(M) x 128(N), K-chunk 32, 8 warps (32x64 each),
// 2 CTAs per SM (independent barrier domains).
#define KC 32
#define AH_OFF 0
#define AL_OFF 8192
#define BH_OFF 16384
#define BL_OFF 24576
#define STAGE_BYTES 32768            // Ah+Al+Bh+Bl (each 128x32 bf16 = 8KB)
#define NSTAGE 3
#define SMEM_BYTES (NSTAGE * STAGE_BYTES)   // 98304 per CTA; 2 CTAs = 192KB/SM

// ---------------------------------------------------------------------------
// Device scratch (no cudaMalloc allowed)
// ---------------------------------------------------------------------------
__device__ __align__(16) __nv_bfloat16 g_x_hi[(size_t)B * L * D];
__device__ __align__(16) __nv_bfloat16 g_x_lo[(size_t)B * L * D];
__device__ __align__(16) __nv_bfloat16 g_xT_hi[(size_t)B * D * LP];
__device__ __align__(16) __nv_bfloat16 g_xT_lo[(size_t)B * D * LP];
__device__ __align__(16) __nv_bfloat16 g_U_hi[(size_t)Y * D];
__device__ __align__(16) __nv_bfloat16 g_U_lo[(size_t)Y * D];
__device__ __align__(16) __nv_bfloat16 g_a_hi[(size_t)B * Y * LP];
__device__ __align__(16) __nv_bfloat16 g_a_lo[(size_t)B * Y * LP];
__device__ float g_bce[B * Y];

// ---------------------------------------------------------------------------
// PTX helpers (base sm_103-legal)
// ---------------------------------------------------------------------------
__device__ __forceinline__ uint32_t smem_u32(const void* p) {
    uint32_t a;
    asm("{ .reg .u64 t; cvta.to.shared.u64 t, %1; cvt.u32.u64 %0, t; }"
        : "=r"(a) : "l"(p));
    return a;
}
__device__ __forceinline__ void cpa16(uint32_t dst, const void* src, int szbytes) {
    asm volatile("cp.async.cg.shared.global [%0], [%1], 16, %2;"
                 :: "r"(dst), "l"(src), "r"(szbytes) : "memory");
}
__device__ __forceinline__ void cpa_commit() {
    asm volatile("cp.async.commit_group;" ::: "memory");
}
template <int N>
__device__ __forceinline__ void cpa_wait() {
    asm volatile("cp.async.wait_group %0;" :: "n"(N) : "memory");
}
__device__ __forceinline__ void ldsm4(uint32_t* r, uint32_t addr) {
    asm volatile("ldmatrix.sync.aligned.m8n8.x4.shared.b16 {%0,%1,%2,%3}, [%4];"
                 : "=r"(r[0]), "=r"(r[1]), "=r"(r[2]), "=r"(r[3]) : "r"(addr));
}
__device__ __forceinline__ void mma16816(float* c, const uint32_t* a,
                                         uint32_t b0, uint32_t b1) {
    asm volatile(
        "mma.sync.aligned.m16n8k16.row.col.f32.bf16.bf16.f32 "
        "{%0,%1,%2,%3}, {%4,%5,%6,%7}, {%8,%9}, {%0,%1,%2,%3};"
        : "+f"(c[0]), "+f"(c[1]), "+f"(c[2]), "+f"(c[3])
        : "r"(a[0]), "r"(a[1]), "r"(a[2]), "r"(a[3]), "r"(b0), "r"(b1));
}

// 64B-row XOR swizzle: row r, 16B-chunk c (0..3)
__device__ __forceinline__ uint32_t swz64(int r, int c) {
    return (uint32_t)(r * 64 + ((c ^ ((r >> 1) & 3)) << 4));
}

// ---------------------------------------------------------------------------
// Chunk loader: Ah/Al + Bh/Bl, each 128 x 32 bf16, cp.async 16B. 256 threads,
// 8 cp.async per thread.
// ---------------------------------------------------------------------------
__device__ __forceinline__ void load_chunk(uint32_t st, int kt,
        const __nv_bfloat16* __restrict__ Ah, const __nv_bfloat16* __restrict__ Al,
        size_t sA, int nA,
        const __nv_bfloat16* __restrict__ Bh, const __nv_bfloat16* __restrict__ Bl,
        size_t sB, int nB, int tid) {
#pragma unroll
    for (int it = 0; it < 2; it++) {
        int idx = tid + it * 256;
        int r = idx >> 2, c = idx & 3;
        uint32_t o = swz64(r, c);
        bool ok = r < nA;
        size_t so = ok ? ((size_t)r * sA + kt + c * 8) : 0;
        cpa16(st + AH_OFF + o, Ah + so, ok ? 16 : 0);
        cpa16(st + AL_OFF + o, Al + so, ok ? 16 : 0);
    }
#pragma unroll
    for (int it = 0; it < 2; it++) {
        int idx = tid + it * 256;
        int r = idx >> 2, c = idx & 3;
        uint32_t o = swz64(r, c);
        bool ok = r < nB;
        size_t so = ok ? ((size_t)r * sB + kt + c * 8) : 0;
        cpa16(st + BH_OFF + o, Bh + so, ok ? 16 : 0);
        cpa16(st + BL_OFF + o, Bl + so, ok ? 16 : 0);
    }
}

// ---------------------------------------------------------------------------
// Core GEMM: C[m<=128, n<=128] = sum_k (Ah+Al)[m,k]*(Bh+Bl)[n,k] (drop lo*lo)
// 256 threads, 8 warps 4(M) x 2(N), warp tile 32x64, m16n8k16 bf16.
// 3-stage cp.async ring, ONE barrier per chunk, B-frag register double-buffer.
// ---------------------------------------------------------------------------
template <int CHUNKS>
__device__ __forceinline__ void gemm_core(
    const __nv_bfloat16* __restrict__ Ah, const __nv_bfloat16* __restrict__ Al,
    size_t sA, int nA,
    const __nv_bfloat16* __restrict__ Bh, const __nv_bfloat16* __restrict__ Bl,
    size_t sB, int nB,
    float* __restrict__ Co, size_t sC, int nrow, int ncol)
{
    extern __shared__ __align__(128) char smem[];
    const uint32_t sb = smem_u32(smem);
    const int tid = threadIdx.x;
    const int lane = tid & 31;
    const int wid = tid >> 5;
    const int warp_m = wid >> 1;     // 0..3 -> 32-row slabs
    const int warp_n = wid & 1;      // 0..1 -> 64-col slabs

    const int rowsel = lane & 15;
    const int colsel = (lane >> 4) & 1;

    // Per-lane row bases and swizzle keys
    int arb[2], arx[2], brb[4], brx[4];
#pragma unroll
    for (int im = 0; im < 2; im++) {
        int r = warp_m * 32 + im * 16 + rowsel;
        arb[im] = r * 64; arx[im] = (r >> 1) & 3;
    }
#pragma unroll
    for (int jn = 0; jn < 4; jn++) {
        int r = warp_n * 64 + jn * 16 + rowsel;
        brb[jn] = r * 64; brx[jn] = (r >> 1) & 3;
    }

    float acc[2][8][4];
#pragma unroll
    for (int i = 0; i < 2; i++)
#pragma unroll
        for (int j = 0; j < 8; j++)
#pragma unroll
            for (int q = 0; q < 4; q++) acc[i][j][q] = 0.0f;

    // Prologue: fill stages 0 and 1
    load_chunk(sb,               0,  Ah, Al, sA, nA, Bh, Bl, sB, nB, tid);
    cpa_commit();
    load_chunk(sb + STAGE_BYTES, KC, Ah, Al, sA, nA, Bh, Bl, sB, nB, tid);
    cpa_commit();

    uint32_t aH[2][4], aL[2][4];
    uint32_t bHb[2][4], bLb[2][4];
    uint32_t stg = 0;   // stage index of chunk c

#pragma unroll 1
    for (int c = 0; c < CHUNKS; c++) {
        if (c + 1 < CHUNKS) cpa_wait<1>(); else cpa_wait<0>();
        __syncthreads();   // stage c ready; all warps done computing c-1

        // Prefetch chunk c+2 into the stage freed by chunk c-1 (overlaps MMA)
        if (c + 2 < CHUNKS) {
            uint32_t nstg = stg + STAGE_BYTES;
            if (nstg >= NSTAGE * STAGE_BYTES) nstg = 0;
            uint32_t pstg = nstg + STAGE_BYTES;
            if (pstg >= NSTAGE * STAGE_BYTES) pstg = 0;
            load_chunk(sb + pstg, (c + 2) * KC, Ah, Al, sA, nA, Bh, Bl, sB, nB, tid);
            cpa_commit();
        }

        const uint32_t s = sb + stg;

        // initial fragments: A(kk=0), B(kk=0,jn=0)
#pragma unroll
        for (int im = 0; im < 2; im++) {
            uint32_t off = (uint32_t)arb[im] + (uint32_t)((colsel ^ arx[im]) << 4);
            ldsm4(aH[im], s + AH_OFF + off);
            ldsm4(aL[im], s + AL_OFF + off);
        }
        {
            uint32_t off = (uint32_t)brb[0] + (uint32_t)((colsel ^ brx[0]) << 4);
            ldsm4(bHb[0], s + BH_OFF + off);
            ldsm4(bLb[0], s + BL_OFF + off);
        }

#pragma unroll
        for (int kk = 0; kk < 2; kk++) {
#pragma unroll
            for (int jn = 0; jn < 4; jn++) {
                const int p = (kk * 4 + jn) & 1;
                // Prefetch next B fragments (register double-buffer)
                if (!(kk == 1 && jn == 3)) {
                    const int nk = (jn == 3) ? kk + 1 : kk;
                    const int njn = (jn == 3) ? 0 : jn + 1;
                    uint32_t off = (uint32_t)brb[njn] +
                        (uint32_t)(((nk * 2 + colsel) ^ brx[njn]) << 4);
                    ldsm4(bHb[p ^ 1], s + BH_OFF + off);
                    ldsm4(bLb[p ^ 1], s + BL_OFF + off);
                }
                // 12 MMAs on current fragments
#pragma unroll
                for (int im = 0; im < 2; im++) {
                    mma16816(acc[im][2 * jn],     aH[im], bHb[p][0], bHb[p][2]);
                    mma16816(acc[im][2 * jn + 1], aH[im], bHb[p][1], bHb[p][3]);
                    mma16816(acc[im][2 * jn],     aH[im], bLb[p][0], bLb[p][2]);
                    mma16816(acc[im][2 * jn + 1], aH[im], bLb[p][1], bLb[p][3]);
                    mma16816(acc[im][2 * jn],     aL[im], bHb[p][0], bHb[p][2]);
                    mma16816(acc[im][2 * jn + 1], aL[im], bHb[p][1], bHb[p][3]);
                }
                // Reload A fragments for kk=1 after last use in kk=0
                if (jn == 3 && kk == 0) {
#pragma unroll
                    for (int im = 0; im < 2; im++) {
                        uint32_t off = (uint32_t)arb[im] +
                            (uint32_t)(((2 + colsel) ^ arx[im]) << 4);
                        ldsm4(aH[im], s + AH_OFF + off);
                        ldsm4(aL[im], s + AL_OFF + off);
                    }
                }
            }
        }

        stg += STAGE_BYTES;
        if (stg >= NSTAGE * STAGE_BYTES) stg = 0;
    }

    // Epilogue: lane l = 4g+t -> rows g, g+8; cols 2t, 2t+1
    const int g = lane >> 2;
    const int t2 = (lane & 3) * 2;
#pragma unroll
    for (int im = 0; im < 2; im++) {
        int r0 = warp_m * 32 + im * 16 + g;
#pragma unroll
        for (int j = 0; j < 8; j++) {
            int cc = warp_n * 64 + j * 8 + t2;
            float* p0 = Co + (size_t)r0 * sC + cc;
            if (r0 < nrow) {
                if (cc < ncol)     p0[0] = acc[im][j][0];
                if (cc + 1 < ncol) p0[1] = acc[im][j][1];
            }
            if (r0 + 8 < nrow) {
                float* p1 = p0 + 8 * sC;
                if (cc < ncol)     p1[0] = acc[im][j][2];
                if (cc + 1 < ncol) p1[1] = acc[im][j][3];
            }
        }
    }
}

// ---------------------------------------------------------------------------
// GEMM1: scores[b,y,l] = U_w[y,:] . x[b,l,:]  (M=Y, N=L, K=D)
// ---------------------------------------------------------------------------
__global__ __launch_bounds__(256, 2)
void gemm1_tc(float* __restrict__ scores) {
    const int b  = blockIdx.z;
    const int m0 = blockIdx.y * 128;
    const int n0 = blockIdx.x * 128;
    int nA = min(Y - m0, 128);
    int nB = min(L - n0, 128);
    gemm_core<D / KC>(
        g_U_hi + (size_t)m0 * D, g_U_lo + (size_t)m0 * D, D, nA,
        g_x_hi + ((size_t)b * L + n0) * D, g_x_lo + ((size_t)b * L + n0) * D, D, nB,
        scores + ((size_t)b * Y + m0) * L + n0, L, nA, nB);
}

// ---------------------------------------------------------------------------
// GEMM2: m[b,y,d] = alpha[b,y,:] . xT[b,d,:]  (M=Y, N=D, K=LP)
// ---------------------------------------------------------------------------
__global__ __launch_bounds__(256, 2)
void gemm2_tc(float* __restrict__ mout) {
    const int b  = blockIdx.z;
    const int m0 = blockIdx.y * 128;
    const int n0 = blockIdx.x * 128;
    int nA = min(Y - m0, 128);
    gemm_core<LP / KC>(
        g_a_hi + ((size_t)b * Y + m0) * LP, g_a_lo + ((size_t)b * Y + m0) * LP, LP, nA,
        g_xT_hi + ((size_t)b * D + n0) * LP, g_xT_lo + ((size_t)b * D + n0) * LP, LP, 128,
        mout + ((size_t)b * Y + m0) * D + n0, D, nA, 128);
}

// ---------------------------------------------------------------------------
// Splitters / transpose
// ---------------------------------------------------------------------------
__global__ __launch_bounds__(256)
void split_u(const float* __restrict__ src) {
    size_t n = (size_t)Y * D;
    for (size_t i = (size_t)blockIdx.x * 256 + threadIdx.x; i < n; i += (size_t)gridDim.x * 256) {
        float v = src[i];
        __nv_bfloat16 h = __float2bfloat16(v);
        float r = v - __bfloat162float(h);
        g_U_hi[i] = h;
        g_U_lo[i] = __float2bfloat16(r);
    }
}

__global__ __launch_bounds__(256)
void split_x(const float* __restrict__ src) {
    size_t n = (size_t)B * L * D;
    for (size_t i = (size_t)blockIdx.x * 256 + threadIdx.x; i < n; i += (size_t)gridDim.x * 256) {
        float v = src[i];
        __nv_bfloat16 h = __float2bfloat16(v);
        float r = v - __bfloat162float(h);
        g_x_hi[i] = h;
        g_x_lo[i] = __float2bfloat16(r);
    }
}

__global__ __launch_bounds__(256)
void transpose_x(const float* __restrict__ x) {
    __shared__ float t[32][33];
    const int b  = blockIdx.z;
    const int l0 = blockIdx.x * 32;
    const int d0 = blockIdx.y * 32;
    const float* xb = x + (size_t)b * L * D;
    const int tx = threadIdx.x & 31;
    const int ty = threadIdx.x >> 5;   // 0..7
#pragma unroll
    for (int i = ty; i < 32; i += 8) {
        int l = l0 + i;
        t[i][tx] = (l < L) ? xb[(size_t)l * D + d0 + tx] : 0.0f;
    }
    __syncthreads();
#pragma unroll
    for (int i = ty; i < 32; i += 8) {
        int d = d0 + i;
        int l = l0 + tx;
        float v = t[tx][i];
        __nv_bfloat16 h = __float2bfloat16(v);
        float r = v - __bfloat162float(h);
        size_t o = ((size_t)b * D + d) * LP + l;
        g_xT_hi[o] = h;
        g_xT_lo[o] = __float2bfloat16(r);
    }
}

// ---------------------------------------------------------------------------
// Softmax over L per row (in place, fp32) + bf16 hi/lo split output (padded)
// ---------------------------------------------------------------------------
__global__ __launch_bounds__(256)
void softmax_rows(float* __restrict__ a) {
    const int row = blockIdx.x;
    float* p = a + (size_t)row * L;
    const int tid = threadIdx.x;

    float vals[10];
    int cnt = 0;
    float mx = -INFINITY;
    for (int i = tid; i < L; i += 256) {
        float v = p[i];
        vals[cnt++] = v;
        mx = fmaxf(mx, v);
    }
    __shared__ float red[256];
    red[tid] = mx; __syncthreads();
    for (int s = 128; s > 0; s >>= 1) {
        if (tid < s) red[tid] = fmaxf(red[tid], red[tid + s]);
        __syncthreads();
    }
    mx = red[0];
    __syncthreads();

    float sum = 0.f;
    for (int c = 0; c < cnt; c++) {
        vals[c] = expf(vals[c] - mx);
        sum += vals[c];
    }
    red[tid] = sum; __syncthreads();
    for (int s = 128; s > 0; s >>= 1) {
        if (tid < s) red[tid] += red[tid + s];
        __syncthreads();
    }
    float inv = 1.0f / red[0];

    size_t ob = (size_t)row * LP;
    cnt = 0;
    for (int i = tid; i < L; i += 256) {
        float v = vals[cnt++] * inv;
        p[i] = v;
        __nv_bfloat16 h = __float2bfloat16(v);
        float r = v - __bfloat162float(h);
        g_a_hi[ob + i] = h;
        g_a_lo[ob + i] = __float2bfloat16(r);
    }
    __nv_bfloat16 z = __float2bfloat16(0.0f);
    for (int i = L + tid; i < LP; i += 256) {
        g_a_hi[ob + i] = z;
        g_a_lo[ob + i] = z;
    }
}

// ---------------------------------------------------------------------------
// Final dot + BCE term per row; loss reduce
// ---------------------------------------------------------------------------
__global__ __launch_bounds__(128)
void final_kernel(const float* __restrict__ mrr,
                  const float* __restrict__ fw,
                  const float* __restrict__ fb,
                  const float* __restrict__ target,
                  float* __restrict__ out_y) {
    const int r = blockIdx.x;
    const int i = r % Y;
    const float* mp = mrr + (size_t)r * D;
    const float* wp = fw + (size_t)i * D;
    const int tid = threadIdx.x;

    float s = 0.f;
    for (int d = tid; d < D; d += 128) s = fmaf(wp[d], mp[d], s);
#pragma unroll
    for (int off = 16; off > 0; off >>= 1) s += __shfl_down_sync(0xffffffffu, s, off);

    __shared__ float sh[4];
    if ((tid & 31) == 0) sh[tid >> 5] = s;
    __syncthreads();
    if (tid == 0) {
        float yv = sh[0] + sh[1] + sh[2] + sh[3] + fb[i];
        out_y[r] = yv;
        float t = target[r];
        g_bce[r] = fmaxf(yv, 0.f) - yv * t + log1pf(expf(-fabsf(yv)));
    }
}

__global__ __launch_bounds__(256)
void loss_reduce(float* __restrict__ out_loss) {
    __shared__ double sh[256];
    double s = 0.0;
    for (int i = threadIdx.x; i < B * Y; i += 256) s += (double)g_bce[i];
    sh[threadIdx.x] = s;
    __syncthreads();
    for (int st = 128; st > 0; st >>= 1) {
        if (threadIdx.x < st) sh[threadIdx.x] += sh[threadIdx.x + st];
        __syncthreads();
    }
    if (threadIdx.x == 0) out_loss[0] = (float)(sh[0] / (double)(B * Y));
}

// ---------------------------------------------------------------------------
// Launch. Output layout: [y (B*Y), loss (1), alpha (B*Y*L), m (B*Y*D)]
// ---------------------------------------------------------------------------
extern "C" void kernel_launch(void* const* d_in, const int* in_sizes, int n_in,
                              void* d_out, int out_size) {
    const float* x      = (const float*)d_in[0];
    const float* target = (const float*)d_in[1];
    // d_in[2] = text_inputs (unused)
    const float* Uw     = (const float*)d_in[3];
    const float* fw     = (const float*)d_in[4];
    const float* fb     = (const float*)d_in[5];

    float* out       = (float*)d_out;
    float* out_y     = out;
    float* out_loss  = out + (size_t)B * Y;
    float* out_alpha = out_loss + 1;
    float* out_m     = out_alpha + (size_t)B * Y * L;

    cudaFuncSetAttribute(gemm1_tc, cudaFuncAttributeMaxDynamicSharedMemorySize, SMEM_BYTES);
    cudaFuncSetAttribute(gemm2_tc, cudaFuncAttributeMaxDynamicSharedMemorySize, SMEM_BYTES);

    split_u<<<2048, 256>>>(Uw);
    split_x<<<8192, 256>>>(x);
    transpose_x<<<dim3(LP / 32, D / 32, B), 256>>>(x);

    gemm1_tc<<<dim3((L + 127) / 128, (Y + 127) / 128, B), 256, SMEM_BYTES>>>(out_alpha);

    softmax_rows<<<B * Y, 256>>>(out_alpha);

    gemm2_tc<<<dim3(D / 128, (Y + 127) / 128, B), 256, SMEM_BYTES>>>(out_m);

    final_kernel<<<B * Y, 128>>>(out_m, fw, fb, target, out_y);
    loss_reduce<<<1, 256>>>(out_loss);
}